// round 5
// baseline (speedup 1.0000x reference)
#include <cuda_runtime.h>

#define NB   2
#define SEQ  2048
#define DM   512
#define NH   8
#define HD   64
#define GHD  (NB*NH)      /* 16 global heads */
#define EPSV 1e-8f

// ---------------- scratch (static device globals: no allocation) ----------------
__device__ float g_Q[GHD*SEQ*HD];
__device__ float g_K[GHD*SEQ*HD];
__device__ float g_V[GHD*SEQ*HD];
__device__ float g_att[NB*SEQ*DM];

// ================= xPos rotary helper =================
__device__ __forceinline__ void rope_pair(float& x1, float& x2, int deven, float pf, bool down)
{
    // scale_vec = (half + 0.4*64)/(1.4*64); inv_freq = 10000^{-half/64}
    float sv   = ((float)deven + 25.6f) * (1.0f / 89.6f);
    float invf = powf(10000.0f, -(float)deven * (1.0f / 64.0f));
    float th   = pf * invf;
    float sn, cs;
    sincosf(th, &sn, &cs);
    float sc = powf(sv, pf * (1.0f / 512.0f));
    if (down) sc = 1.0f / sc;
    float y1 = (x1 * cs - x2 * sn) * sc;
    float y2 = (x2 * cs + x1 * sn) * sc;
    x1 = y1; x2 = y2;
}

// ================= Kernel 1: fused QKV projection + bias + scale + xPos + head split =================
// grid (64 row-blocks, 24 col-blocks of the 1536-wide [Q|K|V] output), 256 threads.
__global__ __launch_bounds__(256) void qkv_kernel(
    const float* __restrict__ X,
    const float* __restrict__ Wq, const float* __restrict__ bq,
    const float* __restrict__ Wk, const float* __restrict__ bk,
    const float* __restrict__ Wv, const float* __restrict__ bv,
    const int*  __restrict__ positions)
{
    __shared__ float Xs[16][68];
    __shared__ float Ws[16][68];

    const int tid = threadIdx.x;
    const int tx  = tid & 15;
    const int ty  = tid >> 4;
    const int r0  = blockIdx.x * 64;
    const int c0  = blockIdx.y * 64;          // 0..1535
    const int kind = c0 / DM;                  // 0=Q 1=K 2=V
    const int cW   = c0 % DM;

    const float* W    = (kind == 0) ? Wq : (kind == 1) ? Wk : Wv;
    const float* bias = (kind == 0) ? bq : (kind == 1) ? bk : bv;

    float acc[4][4];
    #pragma unroll
    for (int i = 0; i < 4; ++i)
        #pragma unroll
        for (int j = 0; j < 4; ++j) acc[i][j] = 0.0f;

    const int lr = tid >> 2;      // 0..63 (row / output col within tile)
    const int lk = tid & 3;       // float4 index within 16-wide K chunk

    for (int kb = 0; kb < DM; kb += 16) {
        float4 xa = *(const float4*)&X[(size_t)(r0 + lr) * DM + kb + lk * 4];
        float4 wa = *(const float4*)&W[(size_t)(cW + lr) * DM + kb + lk * 4];
        Xs[lk*4+0][lr] = xa.x; Xs[lk*4+1][lr] = xa.y; Xs[lk*4+2][lr] = xa.z; Xs[lk*4+3][lr] = xa.w;
        Ws[lk*4+0][lr] = wa.x; Ws[lk*4+1][lr] = wa.y; Ws[lk*4+2][lr] = wa.z; Ws[lk*4+3][lr] = wa.w;
        __syncthreads();

        #pragma unroll
        for (int k = 0; k < 16; ++k) {
            float4 av = *(const float4*)&Xs[k][ty * 4];
            float4 bv4 = *(const float4*)&Ws[k][tx * 4];
            float ar[4] = {av.x, av.y, av.z, av.w};
            float br[4] = {bv4.x, bv4.y, bv4.z, bv4.w};
            #pragma unroll
            for (int i = 0; i < 4; ++i)
                #pragma unroll
                for (int j = 0; j < 4; ++j)
                    acc[i][j] = fmaf(ar[i], br[j], acc[i][j]);
        }
        __syncthreads();
    }

    // epilogue: bias (+Q scale) + xPos rotary, store in [head][s][d] layout
    const int h = cW / HD;                 // head within this 512 block
    const int dbase = tx * 4;              // dim within head (multiple of 4 => aligned pairs)
    float* outbuf = (kind == 0) ? g_Q : (kind == 1) ? g_K : g_V;

    #pragma unroll
    for (int i = 0; i < 4; ++i) {
        int r = r0 + ty * 4 + i;
        int n = r >> 11, s = r & 2047;
        float v0 = acc[i][0] + bias[cW + dbase + 0];
        float v1 = acc[i][1] + bias[cW + dbase + 1];
        float v2 = acc[i][2] + bias[cW + dbase + 2];
        float v3 = acc[i][3] + bias[cW + dbase + 3];
        if (kind != 2) {
            if (kind == 0) { v0 *= 0.125f; v1 *= 0.125f; v2 *= 0.125f; v3 *= 0.125f; }
            float pf = (float)positions[r];
            bool down = (kind == 1);
            rope_pair(v0, v1, dbase + 0, pf, down);
            rope_pair(v2, v3, dbase + 2, pf, down);
        }
        float* dst = outbuf + ((size_t)(n * NH + h) * SEQ + s) * HD + dbase;
        *(float4*)dst = make_float4(v0, v1, v2, v3);
    }
}

// ================= Kernel 2: fused attention (sigmoid + suffix-product gating + AV) =================
// grid (32 row-blocks, 16 heads), 256 threads, dynamic smem.
#define ATTN_SMEM ((4*64*68 + 3*64) * 4)

__global__ __launch_bounds__(256) void attn_kernel(const float* __restrict__ mask)
{
    extern __shared__ float sm[];
    float* QS = sm;                 // [64][68]
    float* KS = QS + 64 * 68;
    float* VS = KS + 64 * 68;
    float* AS = VS + 64 * 68;
    float* VB = AS + 64 * 68;       // boundary V row (64)
    float* WB = VB + 64;            // boundary weights (64)
    float* MS = WB + 64;            // input_mask tile (64)

    const int tid = threadIdx.x;
    const int tx  = tid & 15;
    const int ty  = tid >> 4;
    const int gh  = blockIdx.y;
    const int n   = gh >> 3;
    const int rb  = (int)(gridDim.x - 1 - blockIdx.x);   // heavy blocks launch first
    const int s0  = rb * 64;

    const float* Qg = g_Q + (size_t)gh * SEQ * HD;
    const float* Kg = g_K + (size_t)gh * SEQ * HD;
    const float* Vg = g_V + (size_t)gh * SEQ * HD;

    // load Q tile
    for (int it = tid; it < 64 * 16; it += 256) {
        int rr = it >> 4, f4 = it & 15;
        *(float4*)&QS[rr * 68 + f4 * 4] = *(const float4*)&Qg[(size_t)(s0 + rr) * HD + f4 * 4];
    }
    if (tid < 64) VB[tid] = 0.0f;

    // per-row scan carries (threads 0..63 own row tid)
    float cA = 0.0f;     // A at column (block_end) of previously processed block
    float cP = 1.0f;     // suffix product P(block_end)  (masked tail terms == 1.0f exactly in fp32)

    float out[4][4];
    #pragma unroll
    for (int i = 0; i < 4; ++i)
        #pragma unroll
        for (int j = 0; j < 4; ++j) out[i][j] = 0.0f;

    __syncthreads();

    for (int jb = rb; jb >= 0; --jb) {
        const int lo = jb * 64;

        for (int it = tid; it < 64 * 16; it += 256) {
            int rr = it >> 4, f4 = it & 15;
            *(float4*)&KS[rr * 68 + f4 * 4] = *(const float4*)&Kg[(size_t)(lo + rr) * HD + f4 * 4];
            *(float4*)&VS[rr * 68 + f4 * 4] = *(const float4*)&Vg[(size_t)(lo + rr) * HD + f4 * 4];
        }
        if (tid < 64) MS[tid] = mask[n * SEQ + lo + tid];
        __syncthreads();

        // ---- S = Q K^T (64x64x64) ----
        float sa[4][4];
        #pragma unroll
        for (int i = 0; i < 4; ++i)
            #pragma unroll
            for (int j = 0; j < 4; ++j) sa[i][j] = 0.0f;

        #pragma unroll 4
        for (int d = 0; d < 64; d += 4) {
            float4 qa[4], kb[4];
            #pragma unroll
            for (int i = 0; i < 4; ++i) qa[i] = *(const float4*)&QS[(ty * 4 + i) * 68 + d];
            #pragma unroll
            for (int j = 0; j < 4; ++j) kb[j] = *(const float4*)&KS[(tx * 4 + j) * 68 + d];
            #pragma unroll
            for (int i = 0; i < 4; ++i)
                #pragma unroll
                for (int j = 0; j < 4; ++j) {
                    sa[i][j] = fmaf(qa[i].x, kb[j].x, sa[i][j]);
                    sa[i][j] = fmaf(qa[i].y, kb[j].y, sa[i][j]);
                    sa[i][j] = fmaf(qa[i].z, kb[j].z, sa[i][j]);
                    sa[i][j] = fmaf(qa[i].w, kb[j].w, sa[i][j]);
                }
        }

        // ---- A = sigmoid(S) * mask * causal ----
        #pragma unroll
        for (int i = 0; i < 4; ++i) {
            int sg = s0 + ty * 4 + i;
            #pragma unroll
            for (int j = 0; j < 4; ++j) {
                int tg = lo + tx * 4 + j;
                float a = 0.0f;
                if (tg <= sg)
                    a = __fdividef(MS[tx * 4 + j], 1.0f + __expf(-sa[i][j]));
                AS[(ty * 4 + i) * 68 + tx * 4 + j] = a;
            }
        }
        __syncthreads();

        // ---- per-row suffix-product scan (descending columns, shifted emission) ----
        // w[t] = A[t] * P(t-1);  emitting w[t+1] = A_next * P(t) while processing t.
        if (tid < 64) {
            const int r = tid;
            float lA = cA, lP = cP;
            for (int c = 63; c >= 0; --c) {
                float a  = AS[r * 68 + c];
                float Pn = ((1.0f - a) + EPSV) * lP;
                float w  = lA * Pn;
                if (c == 63) WB[r] = w;
                else         AS[r * 68 + c + 1] = w;
                lA = a; lP = Pn;
            }
            // column `lo` weight deferred to next block; at jb==0 it is w[0] = A[0]*1
            AS[r * 68 + 0] = (jb == 0) ? lA : 0.0f;
            cA = lA; cP = lP;
        }
        __syncthreads();

        // ---- out += W_tile * V_tile  (+ boundary column) ----
        #pragma unroll 8
        for (int c = 0; c < 64; ++c) {
            float a0 = AS[(ty * 4 + 0) * 68 + c];
            float a1 = AS[(ty * 4 + 1) * 68 + c];
            float a2 = AS[(ty * 4 + 2) * 68 + c];
            float a3 = AS[(ty * 4 + 3) * 68 + c];
            float4 v = *(const float4*)&VS[c * 68 + tx * 4];
            out[0][0] = fmaf(a0, v.x, out[0][0]); out[0][1] = fmaf(a0, v.y, out[0][1]);
            out[0][2] = fmaf(a0, v.z, out[0][2]); out[0][3] = fmaf(a0, v.w, out[0][3]);
            out[1][0] = fmaf(a1, v.x, out[1][0]); out[1][1] = fmaf(a1, v.y, out[1][1]);
            out[1][2] = fmaf(a1, v.z, out[1][2]); out[1][3] = fmaf(a1, v.w, out[1][3]);
            out[2][0] = fmaf(a2, v.x, out[2][0]); out[2][1] = fmaf(a2, v.y, out[2][1]);
            out[2][2] = fmaf(a2, v.z, out[2][2]); out[2][3] = fmaf(a2, v.w, out[2][3]);
            out[3][0] = fmaf(a3, v.x, out[3][0]); out[3][1] = fmaf(a3, v.y, out[3][1]);
            out[3][2] = fmaf(a3, v.z, out[3][2]); out[3][3] = fmaf(a3, v.w, out[3][3]);
        }
        {
            float4 v = *(const float4*)&VB[tx * 4];
            #pragma unroll
            for (int i = 0; i < 4; ++i) {
                float w = WB[ty * 4 + i];
                out[i][0] = fmaf(w, v.x, out[i][0]);
                out[i][1] = fmaf(w, v.y, out[i][1]);
                out[i][2] = fmaf(w, v.z, out[i][2]);
                out[i][3] = fmaf(w, v.w, out[i][3]);
            }
        }
        __syncthreads();
        if (tid < 16)
            *(float4*)&VB[tid * 4] = *(const float4*)&VS[0 * 68 + tid * 4];
        __syncthreads();
    }

    // write attended in (N, S, H*64) layout for the output projection
    const int h = gh & 7;
    #pragma unroll
    for (int i = 0; i < 4; ++i) {
        int s = s0 + ty * 4 + i;
        float* dst = g_att + ((size_t)(n * SEQ + s)) * DM + h * HD + tx * 4;
        *(float4*)dst = make_float4(out[i][0], out[i][1], out[i][2], out[i][3]);
    }
}

// ================= Kernel 3: output projection  out = att @ Wo^T + bo =================
__global__ __launch_bounds__(256) void oproj_kernel(
    const float* __restrict__ Wo, const float* __restrict__ bo,
    float* __restrict__ outp)
{
    __shared__ float Xs[16][68];
    __shared__ float Ws[16][68];

    const int tid = threadIdx.x;
    const int tx  = tid & 15;
    const int ty  = tid >> 4;
    const int r0  = blockIdx.x * 64;
    const int c0  = blockIdx.y * 64;

    float acc[4][4];
    #pragma unroll
    for (int i = 0; i < 4; ++i)
        #pragma unroll
        for (int j = 0; j < 4; ++j) acc[i][j] = 0.0f;

    const int lr = tid >> 2;
    const int lk = tid & 3;

    for (int kb = 0; kb < DM; kb += 16) {
        float4 xa = *(const float4*)&g_att[(size_t)(r0 + lr) * DM + kb + lk * 4];
        float4 wa = *(const float4*)&Wo[(size_t)(c0 + lr) * DM + kb + lk * 4];
        Xs[lk*4+0][lr] = xa.x; Xs[lk*4+1][lr] = xa.y; Xs[lk*4+2][lr] = xa.z; Xs[lk*4+3][lr] = xa.w;
        Ws[lk*4+0][lr] = wa.x; Ws[lk*4+1][lr] = wa.y; Ws[lk*4+2][lr] = wa.z; Ws[lk*4+3][lr] = wa.w;
        __syncthreads();

        #pragma unroll
        for (int k = 0; k < 16; ++k) {
            float4 av = *(const float4*)&Xs[k][ty * 4];
            float4 bv4 = *(const float4*)&Ws[k][tx * 4];
            float ar[4] = {av.x, av.y, av.z, av.w};
            float br[4] = {bv4.x, bv4.y, bv4.z, bv4.w};
            #pragma unroll
            for (int i = 0; i < 4; ++i)
                #pragma unroll
                for (int j = 0; j < 4; ++j)
                    acc[i][j] = fmaf(ar[i], br[j], acc[i][j]);
        }
        __syncthreads();
    }

    #pragma unroll
    for (int i = 0; i < 4; ++i) {
        int r = r0 + ty * 4 + i;
        float b0 = bo[c0 + tx * 4 + 0];
        float b1 = bo[c0 + tx * 4 + 1];
        float b2 = bo[c0 + tx * 4 + 2];
        float b3 = bo[c0 + tx * 4 + 3];
        *(float4*)&outp[(size_t)r * DM + c0 + tx * 4] =
            make_float4(acc[i][0] + b0, acc[i][1] + b1, acc[i][2] + b2, acc[i][3] + b3);
    }
}

// ================= host launcher =================
extern "C" void kernel_launch(void* const* d_in, const int* in_sizes, int n_in,
                              void* d_out, int out_size)
{
    // Robust input identification by element count (independent of layer_num placement):
    //   sequence: 2*2048*512, mask/positions: 4096 (mask first in dict order),
    //   weights: 4x 512*512 in order Wq,Wk,Wv,Wo, biases: 4x 512 in order bq,bk,bv,bo.
    const float* seqp = nullptr;
    const float* maskp = nullptr;
    const int*   posp = nullptr;
    const float* W[4] = {nullptr, nullptr, nullptr, nullptr};
    const float* B[4] = {nullptr, nullptr, nullptr, nullptr};
    int nw = 0, nb = 0, n4096 = 0;
    for (int i = 0; i < n_in; ++i) {
        int sz = in_sizes[i];
        if (sz == NB * SEQ * DM) {
            seqp = (const float*)d_in[i];
        } else if (sz == DM * DM) {
            if (nw < 4) W[nw++] = (const float*)d_in[i];
        } else if (sz == DM) {
            if (nb < 4) B[nb++] = (const float*)d_in[i];
        } else if (sz == NB * SEQ) {
            if (n4096 == 0) maskp = (const float*)d_in[i];
            else            posp  = (const int*)d_in[i];
            ++n4096;
        }
    }

    cudaFuncSetAttribute(attn_kernel, cudaFuncAttributeMaxDynamicSharedMemorySize, ATTN_SMEM);

    qkv_kernel<<<dim3(64, 24), 256>>>(seqp, W[0], B[0], W[1], B[1], W[2], B[2], posp);
    attn_kernel<<<dim3(32, 16), 256, ATTN_SMEM>>>(maskp);
    oproj_kernel<<<dim3(64, 8), 256>>>(W[3], B[3], (float*)d_out);
}

// round 7
// speedup vs baseline: 1.0749x; 1.0749x over previous
#include <cuda_runtime.h>

#define NB   2
#define SEQ  2048
#define DM   512
#define NH   8
#define HD   64
#define GHD  (NB*NH)      /* 16 global heads */
#define EPSV 1e-8f

typedef unsigned long long u64;

// ---------------- packed f32x2 helpers (FFMA2 only reachable via PTX) ----------------
__device__ __forceinline__ u64 pack2(float lo, float hi) {
    u64 r;
    asm("mov.b64 %0, {%1, %2};" : "=l"(r)
        : "r"(__float_as_uint(lo)), "r"(__float_as_uint(hi)));
    return r;
}
__device__ __forceinline__ void unpack2(u64 v, float& lo, float& hi) {
    unsigned a, b;
    asm("mov.b64 {%0, %1}, %2;" : "=r"(a), "=r"(b) : "l"(v));
    lo = __uint_as_float(a); hi = __uint_as_float(b);
}
__device__ __forceinline__ void fma2(u64& d, u64 a, u64 b) {
    asm("fma.rn.f32x2 %0, %1, %2, %3;" : "=l"(d) : "l"(a), "l"(b), "l"(d));
}

// ---------------- scratch (static device globals: no allocation) ----------------
__device__ float g_Q[GHD*SEQ*HD];
__device__ float g_K[GHD*SEQ*HD];
__device__ float g_V[GHD*SEQ*HD];
__device__ float g_att[NB*SEQ*DM];

// ================= xPos rotary helper =================
__device__ __forceinline__ void rope_pair(float& x1, float& x2, int deven, float pf, bool down)
{
    float sv   = ((float)deven + 25.6f) * (1.0f / 89.6f);
    float invf = powf(10000.0f, -(float)deven * (1.0f / 64.0f));
    float th   = pf * invf;
    float sn, cs;
    sincosf(th, &sn, &cs);
    float sc = powf(sv, pf * (1.0f / 512.0f));
    if (down) sc = 1.0f / sc;
    float y1 = (x1 * cs - x2 * sn) * sc;
    float y2 = (x2 * cs + x1 * sn) * sc;
    x1 = y1; x2 = y2;
}

// ================= Kernel 1: fused QKV projection + bias + scale + xPos + head split =================
__global__ __launch_bounds__(256) void qkv_kernel(
    const float* __restrict__ X,
    const float* __restrict__ Wq, const float* __restrict__ bq,
    const float* __restrict__ Wk, const float* __restrict__ bk,
    const float* __restrict__ Wv, const float* __restrict__ bv,
    const int*  __restrict__ positions)
{
    __shared__ float Xs[16][68];
    __shared__ float Ws[16][68];

    const int tid = threadIdx.x;
    const int tx  = tid & 15;
    const int ty  = tid >> 4;
    const int r0  = blockIdx.x * 64;
    const int c0  = blockIdx.y * 64;          // 0..1535
    const int kind = c0 / DM;                  // 0=Q 1=K 2=V
    const int cW   = c0 % DM;

    const float* W    = (kind == 0) ? Wq : (kind == 1) ? Wk : Wv;
    const float* bias = (kind == 0) ? bq : (kind == 1) ? bk : bv;

    // packed accumulators: acc2[i2][j] = rows (ty*4+2*i2, ty*4+2*i2+1), col tx*4+j
    u64 acc2[2][4];
    #pragma unroll
    for (int i = 0; i < 2; ++i)
        #pragma unroll
        for (int j = 0; j < 4; ++j) acc2[i][j] = 0ull;

    const int lr = tid >> 2;      // 0..63
    const int lk = tid & 3;       // float4 index within 16-wide K chunk

    for (int kb = 0; kb < DM; kb += 16) {
        float4 xa = *(const float4*)&X[(size_t)(r0 + lr) * DM + kb + lk * 4];
        float4 wa = *(const float4*)&W[(size_t)(cW + lr) * DM + kb + lk * 4];
        Xs[lk*4+0][lr] = xa.x; Xs[lk*4+1][lr] = xa.y; Xs[lk*4+2][lr] = xa.z; Xs[lk*4+3][lr] = xa.w;
        Ws[lk*4+0][lr] = wa.x; Ws[lk*4+1][lr] = wa.y; Ws[lk*4+2][lr] = wa.z; Ws[lk*4+3][lr] = wa.w;
        __syncthreads();

        #pragma unroll
        for (int k = 0; k < 16; ++k) {
            ulonglong2 ap = *(const ulonglong2*)&Xs[k][ty * 4];  // (a0,a1),(a2,a3)
            float4 b = *(const float4*)&Ws[k][tx * 4];
            u64 b0 = pack2(b.x, b.x), b1 = pack2(b.y, b.y);
            u64 b2 = pack2(b.z, b.z), b3 = pack2(b.w, b.w);
            fma2(acc2[0][0], ap.x, b0); fma2(acc2[0][1], ap.x, b1);
            fma2(acc2[0][2], ap.x, b2); fma2(acc2[0][3], ap.x, b3);
            fma2(acc2[1][0], ap.y, b0); fma2(acc2[1][1], ap.y, b1);
            fma2(acc2[1][2], ap.y, b2); fma2(acc2[1][3], ap.y, b3);
        }
        __syncthreads();
    }

    float acc[4][4];
    #pragma unroll
    for (int i2 = 0; i2 < 2; ++i2)
        #pragma unroll
        for (int j = 0; j < 4; ++j)
            unpack2(acc2[i2][j], acc[2*i2][j], acc[2*i2+1][j]);

    // epilogue: bias (+Q scale) + xPos rotary, store in [head][s][d] layout
    const int h = cW / HD;
    const int dbase = tx * 4;
    float* outbuf = (kind == 0) ? g_Q : (kind == 1) ? g_K : g_V;

    #pragma unroll
    for (int i = 0; i < 4; ++i) {
        int r = r0 + ty * 4 + i;
        int n = r >> 11, s = r & 2047;
        float v0 = acc[i][0] + bias[cW + dbase + 0];
        float v1 = acc[i][1] + bias[cW + dbase + 1];
        float v2 = acc[i][2] + bias[cW + dbase + 2];
        float v3 = acc[i][3] + bias[cW + dbase + 3];
        if (kind != 2) {
            if (kind == 0) { v0 *= 0.125f; v1 *= 0.125f; v2 *= 0.125f; v3 *= 0.125f; }
            float pf = (float)positions[r];
            bool down = (kind == 1);
            rope_pair(v0, v1, dbase + 0, pf, down);
            rope_pair(v2, v3, dbase + 2, pf, down);
        }
        float* dst = outbuf + ((size_t)(n * NH + h) * SEQ + s) * HD + dbase;
        *(float4*)dst = make_float4(v0, v1, v2, v3);
    }
}

// ================= Kernel 2: fused attention (sigmoid + suffix-product gating + AV) =================
#define ATTN_SMEM ((4*64*68 + 3*64) * 4)

__global__ __launch_bounds__(256, 2) void attn_kernel(const float* __restrict__ mask)
{
    extern __shared__ float sm[];
    float* QS  = sm;                 // [64 rows][68]
    float* KS  = QS  + 64 * 68;      // [64 rows][68]
    float* VS  = KS  + 64 * 68;      // [64 rows][68]
    float* ASt = VS  + 64 * 68;      // TRANSPOSED weights: [64 cols][68] (index [c][r])
    float* VB  = ASt + 64 * 68;      // boundary V row (64)
    float* WB  = VB + 64;            // boundary weights (64)
    float* MS  = WB + 64;            // input_mask tile (64)

    const int tid = threadIdx.x;
    const int tx  = tid & 15;
    const int ty  = tid >> 4;
    const int gh  = blockIdx.y;
    const int n   = gh >> 3;
    const int rb  = (int)(gridDim.x - 1 - blockIdx.x);   // heavy blocks launch first
    const int s0  = rb * 64;

    const float* Qg = g_Q + (size_t)gh * SEQ * HD;
    const float* Kg = g_K + (size_t)gh * SEQ * HD;
    const float* Vg = g_V + (size_t)gh * SEQ * HD;

    // load Q tile
    for (int it = tid; it < 64 * 16; it += 256) {
        int rr = it >> 4, f4 = it & 15;
        *(float4*)&QS[rr * 68 + f4 * 4] = *(const float4*)&Qg[(size_t)(s0 + rr) * HD + f4 * 4];
    }
    if (tid < 64) VB[tid] = 0.0f;

    // per-row scan carries (threads 0..63 own row tid)
    float cA = 0.0f;
    float cP = 1.0f;

    // packed output accumulators: out2[i2][j] = rows (ty*4+2*i2, +1), col tx*4+j
    u64 out2[2][4];
    #pragma unroll
    for (int i = 0; i < 2; ++i)
        #pragma unroll
        for (int j = 0; j < 4; ++j) out2[i][j] = 0ull;

    __syncthreads();

    for (int jb = rb; jb >= 0; --jb) {
        const int lo = jb * 64;

        for (int it = tid; it < 64 * 16; it += 256) {
            int rr = it >> 4, f4 = it & 15;
            *(float4*)&KS[rr * 68 + f4 * 4] = *(const float4*)&Kg[(size_t)(lo + rr) * HD + f4 * 4];
            *(float4*)&VS[rr * 68 + f4 * 4] = *(const float4*)&Vg[(size_t)(lo + rr) * HD + f4 * 4];
        }
        if (tid < 64) MS[tid] = mask[n * SEQ + lo + tid];
        __syncthreads();

        // ---- S = Q K^T (64x64x64), packed along d ----
        u64 acc2[4][4];
        #pragma unroll
        for (int i = 0; i < 4; ++i)
            #pragma unroll
            for (int j = 0; j < 4; ++j) acc2[i][j] = 0ull;

        #pragma unroll 4
        for (int d = 0; d < 64; d += 4) {
            ulonglong2 qa[4], kb[4];
            #pragma unroll
            for (int i = 0; i < 4; ++i) qa[i] = *(const ulonglong2*)&QS[(ty * 4 + i) * 68 + d];
            #pragma unroll
            for (int j = 0; j < 4; ++j) kb[j] = *(const ulonglong2*)&KS[(tx * 4 + j) * 68 + d];
            #pragma unroll
            for (int i = 0; i < 4; ++i)
                #pragma unroll
                for (int j = 0; j < 4; ++j) {
                    fma2(acc2[i][j], qa[i].x, kb[j].x);
                    fma2(acc2[i][j], qa[i].y, kb[j].y);
                }
        }
        float sa[4][4];
        #pragma unroll
        for (int i = 0; i < 4; ++i)
            #pragma unroll
            for (int j = 0; j < 4; ++j) {
                float l, h; unpack2(acc2[i][j], l, h);
                sa[i][j] = l + h;
            }

        // ---- A = sigmoid(S) * mask * causal, stored TRANSPOSED: ASt[c][r] ----
        #pragma unroll
        for (int j = 0; j < 4; ++j) {
            int tg = lo + tx * 4 + j;
            float mj = MS[tx * 4 + j];
            float w4[4];
            #pragma unroll
            for (int i = 0; i < 4; ++i) {
                int sg = s0 + ty * 4 + i;
                float a = 0.0f;
                if (tg <= sg)
                    a = __fdividef(mj, 1.0f + __expf(-sa[i][j]));
                w4[i] = a;
            }
            *(float4*)&ASt[(tx * 4 + j) * 68 + ty * 4] = make_float4(w4[0], w4[1], w4[2], w4[3]);
        }
        __syncthreads();

        // ---- per-row suffix-product scan (descending columns, shifted emission) ----
        if (tid < 64) {
            const int r = tid;
            float lA = cA, lP = cP;
            for (int c = 63; c >= 0; --c) {
                float a  = ASt[c * 68 + r];
                float Pn = ((1.0f - a) + EPSV) * lP;
                float w  = lA * Pn;
                if (c == 63) WB[r] = w;
                else         ASt[(c + 1) * 68 + r] = w;
                lA = a; lP = Pn;
            }
            ASt[r] = (jb == 0) ? lA : 0.0f;
            cA = lA; cP = lP;
        }
        __syncthreads();

        // ---- out += W_tile * V_tile (packed along row pairs) ----
        #pragma unroll 8
        for (int c = 0; c < 64; ++c) {
            ulonglong2 ap = *(const ulonglong2*)&ASt[c * 68 + ty * 4]; // (a0,a1),(a2,a3)
            float4 v = *(const float4*)&VS[c * 68 + tx * 4];
            u64 v0 = pack2(v.x, v.x), v1 = pack2(v.y, v.y);
            u64 v2 = pack2(v.z, v.z), v3 = pack2(v.w, v.w);
            fma2(out2[0][0], ap.x, v0); fma2(out2[0][1], ap.x, v1);
            fma2(out2[0][2], ap.x, v2); fma2(out2[0][3], ap.x, v3);
            fma2(out2[1][0], ap.y, v0); fma2(out2[1][1], ap.y, v1);
            fma2(out2[1][2], ap.y, v2); fma2(out2[1][3], ap.y, v3);
        }
        {
            ulonglong2 wp = *(const ulonglong2*)&WB[ty * 4];  // (w0,w1),(w2,w3)
            float4 v = *(const float4*)&VB[tx * 4];
            u64 v0 = pack2(v.x, v.x), v1 = pack2(v.y, v.y);
            u64 v2 = pack2(v.z, v.z), v3 = pack2(v.w, v.w);
            fma2(out2[0][0], wp.x, v0); fma2(out2[0][1], wp.x, v1);
            fma2(out2[0][2], wp.x, v2); fma2(out2[0][3], wp.x, v3);
            fma2(out2[1][0], wp.y, v0); fma2(out2[1][1], wp.y, v1);
            fma2(out2[1][2], wp.y, v2); fma2(out2[1][3], wp.y, v3);
        }
        __syncthreads();
        if (tid < 16)
            *(float4*)&VB[tid * 4] = *(const float4*)&VS[0 * 68 + tid * 4];
        __syncthreads();
    }

    // write attended in (N, S, H*64) layout for the output projection
    const int h = gh & 7;
    #pragma unroll
    for (int i2 = 0; i2 < 2; ++i2) {
        float r0v[4], r1v[4];
        #pragma unroll
        for (int j = 0; j < 4; ++j) unpack2(out2[i2][j], r0v[j], r1v[j]);
        int s = s0 + ty * 4 + 2 * i2;
        float* d0 = g_att + ((size_t)(n * SEQ + s)) * DM + h * HD + tx * 4;
        float* d1 = g_att + ((size_t)(n * SEQ + s + 1)) * DM + h * HD + tx * 4;
        *(float4*)d0 = make_float4(r0v[0], r0v[1], r0v[2], r0v[3]);
        *(float4*)d1 = make_float4(r1v[0], r1v[1], r1v[2], r1v[3]);
    }
}

// ================= Kernel 3: output projection  out = att @ Wo^T + bo =================
__global__ __launch_bounds__(256) void oproj_kernel(
    const float* __restrict__ Wo, const float* __restrict__ bo,
    float* __restrict__ outp)
{
    __shared__ float Xs[16][68];
    __shared__ float Ws[16][68];

    const int tid = threadIdx.x;
    const int tx  = tid & 15;
    const int ty  = tid >> 4;
    const int r0  = blockIdx.x * 64;
    const int c0  = blockIdx.y * 64;

    u64 acc2[2][4];
    #pragma unroll
    for (int i = 0; i < 2; ++i)
        #pragma unroll
        for (int j = 0; j < 4; ++j) acc2[i][j] = 0ull;

    const int lr = tid >> 2;
    const int lk = tid & 3;

    for (int kb = 0; kb < DM; kb += 16) {
        float4 xa = *(const float4*)&g_att[(size_t)(r0 + lr) * DM + kb + lk * 4];
        float4 wa = *(const float4*)&Wo[(size_t)(c0 + lr) * DM + kb + lk * 4];
        Xs[lk*4+0][lr] = xa.x; Xs[lk*4+1][lr] = xa.y; Xs[lk*4+2][lr] = xa.z; Xs[lk*4+3][lr] = xa.w;
        Ws[lk*4+0][lr] = wa.x; Ws[lk*4+1][lr] = wa.y; Ws[lk*4+2][lr] = wa.z; Ws[lk*4+3][lr] = wa.w;
        __syncthreads();

        #pragma unroll
        for (int k = 0; k < 16; ++k) {
            ulonglong2 ap = *(const ulonglong2*)&Xs[k][ty * 4];
            float4 b = *(const float4*)&Ws[k][tx * 4];
            u64 b0 = pack2(b.x, b.x), b1 = pack2(b.y, b.y);
            u64 b2 = pack2(b.z, b.z), b3 = pack2(b.w, b.w);
            fma2(acc2[0][0], ap.x, b0); fma2(acc2[0][1], ap.x, b1);
            fma2(acc2[0][2], ap.x, b2); fma2(acc2[0][3], ap.x, b3);
            fma2(acc2[1][0], ap.y, b0); fma2(acc2[1][1], ap.y, b1);
            fma2(acc2[1][2], ap.y, b2); fma2(acc2[1][3], ap.y, b3);
        }
        __syncthreads();
    }

    float acc[4][4];
    #pragma unroll
    for (int i2 = 0; i2 < 2; ++i2)
        #pragma unroll
        for (int j = 0; j < 4; ++j)
            unpack2(acc2[i2][j], acc[2*i2][j], acc[2*i2+1][j]);

    #pragma unroll
    for (int i = 0; i < 4; ++i) {
        int r = r0 + ty * 4 + i;
        float b0 = bo[c0 + tx * 4 + 0];
        float b1 = bo[c0 + tx * 4 + 1];
        float b2 = bo[c0 + tx * 4 + 2];
        float b3 = bo[c0 + tx * 4 + 3];
        *(float4*)&outp[(size_t)r * DM + c0 + tx * 4] =
            make_float4(acc[i][0] + b0, acc[i][1] + b1, acc[i][2] + b2, acc[i][3] + b3);
    }
}

// ================= host launcher =================
extern "C" void kernel_launch(void* const* d_in, const int* in_sizes, int n_in,
                              void* d_out, int out_size)
{
    const float* seqp = nullptr;
    const float* maskp = nullptr;
    const int*   posp = nullptr;
    const float* W[4] = {nullptr, nullptr, nullptr, nullptr};
    const float* B[4] = {nullptr, nullptr, nullptr, nullptr};
    int nw = 0, nb = 0, n4096 = 0;
    for (int i = 0; i < n_in; ++i) {
        int sz = in_sizes[i];
        if (sz == NB * SEQ * DM) {
            seqp = (const float*)d_in[i];
        } else if (sz == DM * DM) {
            if (nw < 4) W[nw++] = (const float*)d_in[i];
        } else if (sz == DM) {
            if (nb < 4) B[nb++] = (const float*)d_in[i];
        } else if (sz == NB * SEQ) {
            if (n4096 == 0) maskp = (const float*)d_in[i];
            else            posp  = (const int*)d_in[i];
            ++n4096;
        }
    }

    cudaFuncSetAttribute(attn_kernel, cudaFuncAttributeMaxDynamicSharedMemorySize, ATTN_SMEM);

    qkv_kernel<<<dim3(64, 24), 256>>>(seqp, W[0], B[0], W[1], B[1], W[2], B[2], posp);
    attn_kernel<<<dim3(32, 16), 256, ATTN_SMEM>>>(maskp);
    oproj_kernel<<<dim3(64, 8), 256>>>(W[3], B[3], (float*)d_out);
}